// round 4
// baseline (speedup 1.0000x reference)
#include <cuda_runtime.h>
#include <cstdint>

#define KMIX 16
#define DDIM 64

typedef unsigned long long ull;

// ------------------------- device scratch (no allocs allowed) ----------------
__device__ float g_P[KMIX * DDIM * DDIM];   // Sigma^{-1} per component (symmetric)
__device__ float g_h[KMIX * DDIM];          // h_k = P_k mu_k
__device__ float g_cst[KMIX];               // log w_k - 0.5*(logdet_k + mu_k.h_k)
__device__ float g_scal[4];                 // [0] = sqrt(1-acp)

// ------------------------- f32x2 helpers (sm_100 packed FP32) ----------------
static __device__ __forceinline__ ull pk2(float a, float b) {
    ull r; asm("mov.b64 %0, {%1, %2};" : "=l"(r) : "f"(a), "f"(b)); return r;
}
static __device__ __forceinline__ float2 up2(ull a) {
    float2 f; asm("mov.b64 {%0, %1}, %2;" : "=f"(f.x), "=f"(f.y) : "l"(a)); return f;
}
static __device__ __forceinline__ ull f2fma(ull a, ull b, ull c) {
    ull r; asm("fma.rn.f32x2 %0, %1, %2, %3;" : "=l"(r) : "l"(a), "l"(b), "l"(c)); return r;
}
static __device__ __forceinline__ ull f2mul(ull a, ull b) {
    ull r; asm("mul.rn.f32x2 %0, %1, %2;" : "=l"(r) : "l"(a), "l"(b)); return r;
}

// =============================================================================
// Setup: invert Sigma_k = (1-acp) I + acp * covs_k  via Gauss-Jordan (SPD,
// min eigenvalue >= 1 by construction so no pivoting). One block per k.
// =============================================================================
__global__ void gm_setup_kernel(const float* __restrict__ means,
                                const float* __restrict__ weights,
                                const float* __restrict__ covs,
                                const float* __restrict__ acp_arr,
                                const int*   __restrict__ t_ptr)
{
    __shared__ float M[DDIM][2 * DDIM + 1];   // [Sigma | I], padded row
    __shared__ float pivs[DDIM];
    __shared__ float hsh[DDIM];
    __shared__ float mush[DDIM];

    const int k = blockIdx.x;
    const int r = threadIdx.x;
    const int t = t_ptr[0];
    const float acp  = acp_arr[t];
    const float sacp = sqrtf(acp);

    for (int c = 0; c < DDIM; c++) {
        float s = acp * covs[(k * DDIM + r) * DDIM + c];
        if (c == r) s += 1.0f - acp;
        M[r][c] = s;
        M[r][DDIM + c] = (c == r) ? 1.0f : 0.0f;
    }
    mush[r] = sacp * means[k * DDIM + r];
    __syncthreads();

    for (int p = 0; p < DDIM; p++) {
        if (r == p) {
            float pv = M[p][p];
            pivs[p] = pv;
            float inv = 1.0f / pv;
            for (int c = 0; c < 2 * DDIM; c++) M[p][c] *= inv;
        }
        __syncthreads();
        if (r != p) {
            float f = M[r][p];
            for (int c = 0; c < 2 * DDIM; c++) M[r][c] -= f * M[p][c];
        }
        __syncthreads();
    }

    // h = P * mu
    float hv = 0.0f;
    for (int c = 0; c < DDIM; c++) hv += M[r][DDIM + c] * mush[c];
    hsh[r] = hv;
    g_h[k * DDIM + r] = hv;
    __syncthreads();

    // coalesced store of P
    for (int idx = r; idx < DDIM * DDIM; idx += DDIM)
        g_P[k * DDIM * DDIM + idx] = M[idx >> 6][DDIM + (idx & 63)];

    if (r == 0) {
        float logdet = 0.0f, muh = 0.0f;
        for (int c = 0; c < DDIM; c++) { logdet += logf(pivs[c]); muh += mush[c] * hsh[c]; }
        g_cst[k] = logf(weights[k]) - 0.5f * (logdet + muh);
        if (k == 0) g_scal[0] = sqrtf(1.0f - acp);
    }
}

// =============================================================================
// Main: 128 threads, 64-batch tile. Thread tile: 8 batch x 4 rows, f32x2 pairs
// along batch. Online softmax over k (flash-attention style).
// =============================================================================
// dynamic smem layout (floats):
//   xs   [64][68]  : x tile, dim-major (xs[j*68+b])            @0      (4352)
//   Ps   [64][68]  : current P_k, row j, cols i                @4352   (4352)
//   hs   [16][64]  : all h_k                                   @8704   (1024)
//   red  [64][17]  : maha partial reduction                    @9728   (1088)
//   csts [16]                                                  @10816
//   cwc  [64], cww [64], sinv [64]                             @10832..
#define SM_XS   0
#define SM_PS   4352
#define SM_HS   8704
#define SM_RED  9728
#define SM_CST  10816
#define SM_CWC  10832
#define SM_CWW  10896
#define SM_SNV  10960
#define SM_TOT  11024   // floats -> 44096 bytes

__global__ __launch_bounds__(128, 4)
void gm_main_kernel(const float* __restrict__ x, float* __restrict__ out)
{
    extern __shared__ float sm[];
    float* xs   = sm + SM_XS;
    float* Ps   = sm + SM_PS;
    float* hsm  = sm + SM_HS;
    float* red  = sm + SM_RED;
    float* csts = sm + SM_CST;
    float* cwc  = sm + SM_CWC;
    float* cww  = sm + SM_CWW;
    float* sinv = sm + SM_SNV;

    const int tid = threadIdx.x;
    const int tx = tid & 7;        // batch group: b0 = 8*tx
    const int ty = tid >> 3;       // row group:   i0 = 4*ty
    const int bbase = blockIdx.x * 64;

    // ---- load x tile, transposed to dim-major ----
    for (int u = tid; u < 64 * 16; u += 128) {
        int b = u >> 4, d4 = (u & 15) << 2;
        float4 v = *(const float4*)(x + (bbase + b) * 64 + d4);
        xs[(d4 + 0) * 68 + b] = v.x;
        xs[(d4 + 1) * 68 + b] = v.y;
        xs[(d4 + 2) * 68 + b] = v.z;
        xs[(d4 + 3) * 68 + b] = v.w;
    }
    for (int u = tid; u < KMIX * DDIM; u += 128) hsm[u] = g_h[u];
    if (tid < KMIX) csts[tid] = g_cst[tid];
    const float sconst = g_scal[0];

    float m_b = -1e30f, Z_b = 0.0f;      // softmax state (threads tid<64, b = tid)
    ull acc[4][4];                        // acc[q = i][p = b-pair]
    #pragma unroll
    for (int q = 0; q < 4; q++)
        #pragma unroll
        for (int p = 0; p < 4; p++) acc[q][p] = 0ULL;

    const float* xrow = xs + 8 * tx;
    const float* prow = Ps + 4 * ty;
    __syncthreads();

    for (int k = 0; k < KMIX; k++) {
        // ---- stream P_k into shared (L2-resident, 16 KB) ----
        for (int u = tid; u < 1024; u += 128) {
            float4 v = *(const float4*)(g_P + k * 4096 + u * 4);
            *(float4*)(Ps + (u >> 4) * 68 + ((u & 15) << 2)) = v;
        }
        __syncthreads();

        // ---- v[i][b] = sum_j P[j][i] * x[j][b]  (P symmetric => v = P x) ----
        ull v[4][4];
        #pragma unroll
        for (int q = 0; q < 4; q++)
            #pragma unroll
            for (int p = 0; p < 4; p++) v[q][p] = 0ULL;

        #pragma unroll
        for (int j = 0; j < 64; j++) {
            ulonglong2 xa = *(const ulonglong2*)(xrow + j * 68);      // b0..b3
            ulonglong2 xb = *(const ulonglong2*)(xrow + j * 68 + 4);  // b4..b7
            float p0 = prow[j * 68 + 0];
            float p1 = prow[j * 68 + 1];
            float p2 = prow[j * 68 + 2];
            float p3 = prow[j * 68 + 3];
            ull pp;
            pp = pk2(p0, p0);
            v[0][0] = f2fma(pp, xa.x, v[0][0]); v[0][1] = f2fma(pp, xa.y, v[0][1]);
            v[0][2] = f2fma(pp, xb.x, v[0][2]); v[0][3] = f2fma(pp, xb.y, v[0][3]);
            pp = pk2(p1, p1);
            v[1][0] = f2fma(pp, xa.x, v[1][0]); v[1][1] = f2fma(pp, xa.y, v[1][1]);
            v[1][2] = f2fma(pp, xb.x, v[1][2]); v[1][3] = f2fma(pp, xb.y, v[1][3]);
            pp = pk2(p2, p2);
            v[2][0] = f2fma(pp, xa.x, v[2][0]); v[2][1] = f2fma(pp, xa.y, v[2][1]);
            v[2][2] = f2fma(pp, xb.x, v[2][2]); v[2][3] = f2fma(pp, xb.y, v[2][3]);
            pp = pk2(p3, p3);
            v[3][0] = f2fma(pp, xa.x, v[3][0]); v[3][1] = f2fma(pp, xa.y, v[3][1]);
            v[3][2] = f2fma(pp, xb.x, v[3][2]); v[3][3] = f2fma(pp, xb.y, v[3][3]);
        }

        // ---- epilogue: g = v - h, maha partials S_b = sum_i (g_i - h_i) x_i ----
        float part[8];
        #pragma unroll
        for (int p = 0; p < 8; p++) part[p] = 0.0f;

        #pragma unroll
        for (int q = 0; q < 4; q++) {
            float hq = hsm[k * 64 + 4 * ty + q];
            #pragma unroll
            for (int p = 0; p < 4; p++) {
                float2 vv = up2(v[q][p]);
                float x0 = xs[(4 * ty + q) * 68 + 8 * tx + 2 * p];
                float x1 = xs[(4 * ty + q) * 68 + 8 * tx + 2 * p + 1];
                float g0 = vv.x - hq, g1 = vv.y - hq;
                part[2 * p]     += (g0 - hq) * x0;
                part[2 * p + 1] += (g1 - hq) * x1;
                v[q][p] = pk2(g0, g1);          // now holds g
            }
        }
        #pragma unroll
        for (int p = 0; p < 8; p++) red[(8 * tx + p) * 17 + ty] = part[p];
        __syncthreads();

        // ---- per-batch logit + online softmax (one thread per batch elem) ----
        if (tid < 64) {
            float ssum = 0.0f;
            #pragma unroll
            for (int y = 0; y < 16; y++) ssum += red[tid * 17 + y];
            float logit = csts[k] - 0.5f * ssum;
            float mn = fmaxf(m_b, logit);
            float c = __expf(m_b - mn);
            float w = __expf(logit - mn);
            Z_b = Z_b * c + w;
            m_b = mn;
            cwc[tid] = c;
            cww[tid] = w;
        }
        __syncthreads();

        // ---- rescale + accumulate: acc = acc*c + w*g ----
        #pragma unroll
        for (int p = 0; p < 4; p++) {
            ull cc = *(const ull*)(cwc + 8 * tx + 2 * p);
            ull ww = *(const ull*)(cww + 8 * tx + 2 * p);
            #pragma unroll
            for (int q = 0; q < 4; q++)
                acc[q][p] = f2fma(acc[q][p], cc, f2mul(v[q][p], ww));
        }
    }

    // ---- finalize: out = sqrt(1-acp) * acc / Z ----
    if (tid < 64) sinv[tid] = sconst / Z_b;
    __syncthreads();

    float* os = xs;   // reuse xs as output staging (all xs reads are done)
    #pragma unroll
    for (int p = 0; p < 4; p++) {
        ull sc = *(const ull*)(sinv + 8 * tx + 2 * p);
        #pragma unroll
        for (int q = 0; q < 4; q++) {
            float2 r = up2(f2mul(acc[q][p], sc));
            os[(8 * tx + 2 * p)     * 68 + 4 * ty + q] = r.x;
            os[(8 * tx + 2 * p + 1) * 68 + 4 * ty + q] = r.y;
        }
    }
    __syncthreads();

    for (int u = tid; u < 1024; u += 128) {
        int b = u >> 4, i4 = (u & 15) << 2;
        float4 vv = *(const float4*)(os + b * 68 + i4);
        *(float4*)(out + (bbase + b) * 64 + i4) = vv;
    }
}

// =============================================================================
extern "C" void kernel_launch(void* const* d_in, const int* in_sizes, int n_in,
                              void* d_out, int out_size)
{
    const float* x       = (const float*)d_in[0];
    const float* means   = (const float*)d_in[1];
    const float* weights = (const float*)d_in[2];
    const float* covs    = (const float*)d_in[3];
    const float* acp     = (const float*)d_in[4];
    const int*   t       = (const int*)d_in[5];

    gm_setup_kernel<<<KMIX, DDIM>>>(means, weights, covs, acp, t);

    const int B = in_sizes[0] / DDIM;          // 65536
    gm_main_kernel<<<B / 64, 128, SM_TOT * 4>>>(x, (float*)d_out);
}

// round 5
// speedup vs baseline: 1.0075x; 1.0075x over previous
#include <cuda_runtime.h>
#include <cstdint>

#define KMIX 16
#define DDIM 64

typedef unsigned long long ull;

// ------------------------- device scratch (no allocs allowed) ----------------
__device__ float g_P[KMIX * DDIM * DDIM];   // Sigma^{-1} per component (symmetric)
__device__ float g_h[KMIX * DDIM];          // h_k = P_k mu_k
__device__ float g_cst[KMIX];               // log w_k - 0.5*(logdet_k + mu_k.h_k)
__device__ float g_scal[4];                 // [0] = sqrt(1-acp)

// ------------------------- f32x2 helpers (sm_100 packed FP32) ----------------
static __device__ __forceinline__ ull pk2(float a, float b) {
    ull r; asm("mov.b64 %0, {%1, %2};" : "=l"(r) : "f"(a), "f"(b)); return r;
}
static __device__ __forceinline__ float2 up2(ull a) {
    float2 f; asm("mov.b64 {%0, %1}, %2;" : "=f"(f.x), "=f"(f.y) : "l"(a)); return f;
}
static __device__ __forceinline__ ull f2fma(ull a, ull b, ull c) {
    ull r; asm("fma.rn.f32x2 %0, %1, %2, %3;" : "=l"(r) : "l"(a), "l"(b), "l"(c)); return r;
}
static __device__ __forceinline__ ull f2mul(ull a, ull b) {
    ull r; asm("mul.rn.f32x2 %0, %1, %2;" : "=l"(r) : "l"(a), "l"(b)); return r;
}

// =============================================================================
// Setup: invert Sigma_k = (1-acp) I + acp * covs_k  via Gauss-Jordan (SPD,
// min eigenvalue >= 1 by construction so no pivoting). One block per k.
// =============================================================================
__global__ void gm_setup_kernel(const float* __restrict__ means,
                                const float* __restrict__ weights,
                                const float* __restrict__ covs,
                                const float* __restrict__ acp_arr,
                                const int*   __restrict__ t_ptr)
{
    __shared__ float M[DDIM][2 * DDIM + 1];   // [Sigma | I], padded row
    __shared__ float pivs[DDIM];
    __shared__ float hsh[DDIM];
    __shared__ float mush[DDIM];

    const int k = blockIdx.x;
    const int r = threadIdx.x;
    const int t = t_ptr[0];
    const float acp  = acp_arr[t];
    const float sacp = sqrtf(acp);

    for (int c = 0; c < DDIM; c++) {
        float s = acp * covs[(k * DDIM + r) * DDIM + c];
        if (c == r) s += 1.0f - acp;
        M[r][c] = s;
        M[r][DDIM + c] = (c == r) ? 1.0f : 0.0f;
    }
    mush[r] = sacp * means[k * DDIM + r];
    __syncthreads();

    for (int p = 0; p < DDIM; p++) {
        if (r == p) {
            float pv = M[p][p];
            pivs[p] = pv;
            float inv = 1.0f / pv;
            for (int c = 0; c < 2 * DDIM; c++) M[p][c] *= inv;
        }
        __syncthreads();
        if (r != p) {
            float f = M[r][p];
            for (int c = 0; c < 2 * DDIM; c++) M[r][c] -= f * M[p][c];
        }
        __syncthreads();
    }

    // h = P * mu
    float hv = 0.0f;
    for (int c = 0; c < DDIM; c++) hv += M[r][DDIM + c] * mush[c];
    hsh[r] = hv;
    g_h[k * DDIM + r] = hv;
    __syncthreads();

    // coalesced store of P
    for (int idx = r; idx < DDIM * DDIM; idx += DDIM)
        g_P[k * DDIM * DDIM + idx] = M[idx >> 6][DDIM + (idx & 63)];

    if (r == 0) {
        float logdet = 0.0f, muh = 0.0f;
        for (int c = 0; c < DDIM; c++) { logdet += logf(pivs[c]); muh += mush[c] * hsh[c]; }
        g_cst[k] = logf(weights[k]) - 0.5f * (logdet + muh);
        if (k == 0) g_scal[0] = sqrtf(1.0f - acp);
    }
}

// =============================================================================
// Main: 128 threads, 64-batch tile. Thread tile: 8 batch x 4 rows, f32x2 pairs
// along batch. Online softmax over k (flash-attention style).
// =============================================================================
// dynamic smem layout (floats):
//   xs   [64][68]  : x tile, dim-major (xs[j*68+b])            @0      (4352)
//   Ps   [64][68]  : current P_k, row j, cols i                @4352   (4352)
//   hs   [16][64]  : all h_k                                   @8704   (1024)
//   red  [64][17]  : maha partial reduction                    @9728   (1088)
//   csts [16]                                                  @10816
//   cwc  [64], cww [64], sinv [64]                             @10832..
#define SM_XS   0
#define SM_PS   4352
#define SM_HS   8704
#define SM_RED  9728
#define SM_CST  10816
#define SM_CWC  10832
#define SM_CWW  10896
#define SM_SNV  10960
#define SM_TOT  11024   // floats -> 44096 bytes

__global__ __launch_bounds__(128, 4)
void gm_main_kernel(const float* __restrict__ x, float* __restrict__ out)
{
    extern __shared__ float sm[];
    float* xs   = sm + SM_XS;
    float* Ps   = sm + SM_PS;
    float* hsm  = sm + SM_HS;
    float* red  = sm + SM_RED;
    float* csts = sm + SM_CST;
    float* cwc  = sm + SM_CWC;
    float* cww  = sm + SM_CWW;
    float* sinv = sm + SM_SNV;

    const int tid = threadIdx.x;
    const int tx = tid & 7;        // batch group: b0 = 8*tx
    const int ty = tid >> 3;       // row group:   i0 = 4*ty
    const int bbase = blockIdx.x * 64;

    // ---- load x tile, transposed to dim-major ----
    for (int u = tid; u < 64 * 16; u += 128) {
        int b = u >> 4, d4 = (u & 15) << 2;
        float4 v = *(const float4*)(x + (bbase + b) * 64 + d4);
        xs[(d4 + 0) * 68 + b] = v.x;
        xs[(d4 + 1) * 68 + b] = v.y;
        xs[(d4 + 2) * 68 + b] = v.z;
        xs[(d4 + 3) * 68 + b] = v.w;
    }
    for (int u = tid; u < KMIX * DDIM; u += 128) hsm[u] = g_h[u];
    if (tid < KMIX) csts[tid] = g_cst[tid];
    const float sconst = g_scal[0];

    float m_b = -1e30f, Z_b = 0.0f;      // softmax state (threads tid<64, b = tid)
    ull acc[4][4];                        // acc[q = i][p = b-pair]
    #pragma unroll
    for (int q = 0; q < 4; q++)
        #pragma unroll
        for (int p = 0; p < 4; p++) acc[q][p] = 0ULL;

    const float* xrow = xs + 8 * tx;
    const float* prow = Ps + 4 * ty;
    __syncthreads();

    for (int k = 0; k < KMIX; k++) {
        // ---- stream P_k into shared (L2-resident, 16 KB) ----
        for (int u = tid; u < 1024; u += 128) {
            float4 v = *(const float4*)(g_P + k * 4096 + u * 4);
            *(float4*)(Ps + (u >> 4) * 68 + ((u & 15) << 2)) = v;
        }
        __syncthreads();

        // ---- v[i][b] = sum_j P[j][i] * x[j][b]  (P symmetric => v = P x) ----
        ull v[4][4];
        #pragma unroll
        for (int q = 0; q < 4; q++)
            #pragma unroll
            for (int p = 0; p < 4; p++) v[q][p] = 0ULL;

        #pragma unroll
        for (int j = 0; j < 64; j++) {
            ulonglong2 xa = *(const ulonglong2*)(xrow + j * 68);      // b0..b3
            ulonglong2 xb = *(const ulonglong2*)(xrow + j * 68 + 4);  // b4..b7
            float p0 = prow[j * 68 + 0];
            float p1 = prow[j * 68 + 1];
            float p2 = prow[j * 68 + 2];
            float p3 = prow[j * 68 + 3];
            ull pp;
            pp = pk2(p0, p0);
            v[0][0] = f2fma(pp, xa.x, v[0][0]); v[0][1] = f2fma(pp, xa.y, v[0][1]);
            v[0][2] = f2fma(pp, xb.x, v[0][2]); v[0][3] = f2fma(pp, xb.y, v[0][3]);
            pp = pk2(p1, p1);
            v[1][0] = f2fma(pp, xa.x, v[1][0]); v[1][1] = f2fma(pp, xa.y, v[1][1]);
            v[1][2] = f2fma(pp, xb.x, v[1][2]); v[1][3] = f2fma(pp, xb.y, v[1][3]);
            pp = pk2(p2, p2);
            v[2][0] = f2fma(pp, xa.x, v[2][0]); v[2][1] = f2fma(pp, xa.y, v[2][1]);
            v[2][2] = f2fma(pp, xb.x, v[2][2]); v[2][3] = f2fma(pp, xb.y, v[2][3]);
            pp = pk2(p3, p3);
            v[3][0] = f2fma(pp, xa.x, v[3][0]); v[3][1] = f2fma(pp, xa.y, v[3][1]);
            v[3][2] = f2fma(pp, xb.x, v[3][2]); v[3][3] = f2fma(pp, xb.y, v[3][3]);
        }

        // ---- epilogue: g = v - h, maha partials S_b = sum_i (g_i - h_i) x_i ----
        float part[8];
        #pragma unroll
        for (int p = 0; p < 8; p++) part[p] = 0.0f;

        #pragma unroll
        for (int q = 0; q < 4; q++) {
            float hq = hsm[k * 64 + 4 * ty + q];
            #pragma unroll
            for (int p = 0; p < 4; p++) {
                float2 vv = up2(v[q][p]);
                float x0 = xs[(4 * ty + q) * 68 + 8 * tx + 2 * p];
                float x1 = xs[(4 * ty + q) * 68 + 8 * tx + 2 * p + 1];
                float g0 = vv.x - hq, g1 = vv.y - hq;
                part[2 * p]     += (g0 - hq) * x0;
                part[2 * p + 1] += (g1 - hq) * x1;
                v[q][p] = pk2(g0, g1);          // now holds g
            }
        }
        #pragma unroll
        for (int p = 0; p < 8; p++) red[(8 * tx + p) * 17 + ty] = part[p];
        __syncthreads();

        // ---- per-batch logit + online softmax (one thread per batch elem) ----
        if (tid < 64) {
            float ssum = 0.0f;
            #pragma unroll
            for (int y = 0; y < 16; y++) ssum += red[tid * 17 + y];
            float logit = csts[k] - 0.5f * ssum;
            float mn = fmaxf(m_b, logit);
            float c = __expf(m_b - mn);
            float w = __expf(logit - mn);
            Z_b = Z_b * c + w;
            m_b = mn;
            cwc[tid] = c;
            cww[tid] = w;
        }
        __syncthreads();

        // ---- rescale + accumulate: acc = acc*c + w*g ----
        #pragma unroll
        for (int p = 0; p < 4; p++) {
            ull cc = *(const ull*)(cwc + 8 * tx + 2 * p);
            ull ww = *(const ull*)(cww + 8 * tx + 2 * p);
            #pragma unroll
            for (int q = 0; q < 4; q++)
                acc[q][p] = f2fma(acc[q][p], cc, f2mul(v[q][p], ww));
        }
    }

    // ---- finalize: out = sqrt(1-acp) * acc / Z ----
    if (tid < 64) sinv[tid] = sconst / Z_b;
    __syncthreads();

    float* os = xs;   // reuse xs as output staging (all xs reads are done)
    #pragma unroll
    for (int p = 0; p < 4; p++) {
        ull sc = *(const ull*)(sinv + 8 * tx + 2 * p);
        #pragma unroll
        for (int q = 0; q < 4; q++) {
            float2 r = up2(f2mul(acc[q][p], sc));
            os[(8 * tx + 2 * p)     * 68 + 4 * ty + q] = r.x;
            os[(8 * tx + 2 * p + 1) * 68 + 4 * ty + q] = r.y;
        }
    }
    __syncthreads();

    for (int u = tid; u < 1024; u += 128) {
        int b = u >> 4, i4 = (u & 15) << 2;
        float4 vv = *(const float4*)(os + b * 68 + i4);
        *(float4*)(out + (bbase + b) * 64 + i4) = vv;
    }
}

// =============================================================================
extern "C" void kernel_launch(void* const* d_in, const int* in_sizes, int n_in,
                              void* d_out, int out_size)
{
    const float* x       = (const float*)d_in[0];
    const float* means   = (const float*)d_in[1];
    const float* weights = (const float*)d_in[2];
    const float* covs    = (const float*)d_in[3];
    const float* acp     = (const float*)d_in[4];
    const int*   t       = (const int*)d_in[5];

    gm_setup_kernel<<<KMIX, DDIM>>>(means, weights, covs, acp, t);

    const int B = in_sizes[0] / DDIM;          // 65536
    gm_main_kernel<<<B / 64, 128, SM_TOT * 4>>>(x, (float*)d_out);
}